// round 14
// baseline (speedup 1.0000x reference)
#include <cuda_runtime.h>
#include <cuda_bf16.h>
#include <cstdint>

// Swin window attention. R14 = R13 with attention+projection FUSED per window:
// one block per window (4096 x 256thr, 8 warps = 2/head); O stays in smem,
// proj runs in-place with the pipelined-W GEMM core. g_att eliminated.
// B=64, H=W=56, C=128, heads=4, hd=32, ws=7, L=49.

#define TOKENS   200704
#define NWIN     4096
#define QKV_ELEMS (3ull * 16384ull * 49ull * 32ull)
#define COMB_ELEMS (64 * 4 * 2401)   // [win][head][ij]

__device__ float g_qkv[QKV_ELEMS];   // tf32 bits: [(s*16384 + wh)*49 + l]*32 + d
__device__ float g_comb[COMB_ELEMS]; // relt[relidx[ij]][head] + mask[win][ij]

// ---------------------------------------------------------------------------
__device__ __forceinline__ uint32_t f2tf32(float x) {
    uint32_t r;
    asm("cvt.rna.tf32.f32 %0, %1;" : "=r"(r) : "f"(x));
    return r;
}
__device__ __forceinline__ void mma_tf32(float (&d)[4], const uint32_t* a, const uint32_t* b) {
    asm volatile("mma.sync.aligned.m16n8k8.row.col.f32.tf32.tf32.f32 "
                 "{%0,%1,%2,%3}, {%4,%5,%6,%7}, {%8,%9}, {%0,%1,%2,%3};"
                 : "+f"(d[0]), "+f"(d[1]), "+f"(d[2]), "+f"(d[3])
                 : "r"(a[0]), "r"(a[1]), "r"(a[2]), "r"(a[3]), "r"(b[0]), "r"(b[1]));
}

#define A_STR 132
#define SM_A_BYTES (128 * A_STR * 4)   // 67584 (qkv kernel)

// Fused kernel smem (words): Q [64][132] @0, K [64][132] @8448,
// P (alias Q+K+pad) 4 x [64][72] @0 (18432), V [64][136] @18432,
// O (alias P, dead) [64][132] @0.
#define FA_WORDS (18432 + 64 * 136)      // 27136
#define FA_BYTES (FA_WORDS * 4)          // 108544

// ---------------------------------------------------------------------------
// Kernel 0: combine relative-position bias and window mask.
// ---------------------------------------------------------------------------
__global__ __launch_bounds__(256) void combine_bias(
    const int* __restrict__ relidx, const float* __restrict__ mask,
    const float* __restrict__ relt)
{
    int i = blockIdx.x * 256 + threadIdx.x;
    if (i < COMB_ELEMS) {
        int ij = i % 2401;
        int wh = i / 2401;
        int head = wh & 3, win = wh >> 2;
        g_comb[i] = __ldg(relt + __ldg(relidx + ij) * 4 + head)
                  + __ldg(mask + (size_t)win * 2401 + ij);
    }
}

// ---------------------------------------------------------------------------
// Kernel 1: QKV GEMM (unchanged from R13). grid=1568, 256 threads.
// ---------------------------------------------------------------------------
__global__ __launch_bounds__(256, 2) void qkv_gemm_mma(
    const float* __restrict__ A, const float* __restrict__ W,
    const float* __restrict__ bias)
{
    extern __shared__ uint32_t As[];

    int tid = threadIdx.x, bm = blockIdx.x;
    int lane = tid & 31, warp = tid >> 5;
    int g = lane >> 2, t = lane & 3;
    int m0 = (warp >> 2) * 64, n0 = (warp & 3) * 32;
    int head = warp & 3;

    {
        const float4* Ap = (const float4*)(A + (size_t)bm * 128 * 128);
        for (int i = tid; i < 4096; i += 256) {
            int r = i >> 5, c = (i & 31) << 2;
            float4 v = Ap[i];
            uint4 u = make_uint4(f2tf32(v.x), f2tf32(v.y), f2tf32(v.z), f2tf32(v.w));
            *(uint4*)&As[r * A_STR + c] = u;
        }
    }

    int whbase[8], lwin8[8];
#pragma unroll
    for (int mt = 0; mt < 4; mt++)
#pragma unroll
        for (int h = 0; h < 2; h++) {
            int m = bm * 128 + m0 + mt * 16 + g + h * 8;
            int bimg = m / 3136;
            int rem  = m - bimg * 3136;
            int y = rem / 56, xx = rem - y * 56;
            int nhi = y / 7,  wy = y - nhi * 7;
            int nwi = xx / 7, wx = xx - nwi * 7;
            whbase[mt * 2 + h] = (bimg * 64 + nhi * 8 + nwi) * 4 + head;
            lwin8[mt * 2 + h]  = wy * 7 + wx;
        }
    __syncthreads();

#pragma unroll 1
    for (int s = 0; s < 3; s++) {
        const float* Wp = W + s * 128 + n0 + g;
        float acc[4][4][4] = {};

        uint32_t bv[8];
        {
            const float* w0 = Wp + (size_t)t * 384;
            const float* w1 = w0 + 4 * 384;
#pragma unroll
            for (int nt = 0; nt < 4; nt++) {
                bv[nt]     = f2tf32(__ldg(w0 + nt * 8));
                bv[4 + nt] = f2tf32(__ldg(w1 + nt * 8));
            }
        }
#pragma unroll
        for (int k0 = 0; k0 < 128; k0 += 8) {
            uint32_t bc[8];
#pragma unroll
            for (int j = 0; j < 8; j++) bc[j] = bv[j];
            if (k0 < 120) {
                const float* w0 = Wp + (size_t)(k0 + 8 + t) * 384;
                const float* w1 = w0 + 4 * 384;
#pragma unroll
                for (int nt = 0; nt < 4; nt++) {
                    bv[nt]     = f2tf32(__ldg(w0 + nt * 8));
                    bv[4 + nt] = f2tf32(__ldg(w1 + nt * 8));
                }
            }
            uint32_t a[4][4];
#pragma unroll
            for (int mt = 0; mt < 4; mt++) {
                int base = (m0 + mt * 16 + g) * A_STR + k0 + t;
                a[mt][0] = As[base];
                a[mt][1] = As[base + 8 * A_STR];
                a[mt][2] = As[base + 4];
                a[mt][3] = As[base + 8 * A_STR + 4];
            }
#pragma unroll
            for (int mt = 0; mt < 4; mt++)
#pragma unroll
                for (int nt = 0; nt < 4; nt++) {
                    uint32_t bb2[2] = {bc[nt], bc[4 + nt]};
                    mma_tf32(acc[mt][nt], a[mt], bb2);
                }
        }

        float bb[4][2];
#pragma unroll
        for (int nt = 0; nt < 4; nt++) {
            int d = nt * 8 + 2 * t;
            bb[nt][0] = bias[s * 128 + head * 32 + d];
            bb[nt][1] = bias[s * 128 + head * 32 + d + 1];
        }
#pragma unroll
        for (int mt = 0; mt < 4; mt++)
#pragma unroll
            for (int h = 0; h < 2; h++) {
                int idx = mt * 2 + h;
                size_t dst0 = ((size_t)(s * 16384 + whbase[idx]) * 49 + lwin8[idx]) * 32;
#pragma unroll
                for (int nt = 0; nt < 4; nt++) {
                    int d = nt * 8 + 2 * t;
                    uint2 v = make_uint2(f2tf32(acc[mt][nt][2 * h]     + bb[nt][0]),
                                         f2tf32(acc[mt][nt][2 * h + 1] + bb[nt][1]));
                    *(uint2*)&g_qkv[dst0 + d] = v;
                }
            }
    }
}

// ---------------------------------------------------------------------------
// Kernel 2: FUSED attention + projection. One block per window, 256 threads,
// 8 warps (2 per head). In-register softmax; O kept in smem; proj in-place.
// ---------------------------------------------------------------------------
__global__ __launch_bounds__(256, 2) void attnproj_mma(
    const float* __restrict__ proj_w, const float* __restrict__ proj_b,
    float* __restrict__ out)
{
    extern __shared__ uint32_t dyn[];
    uint32_t* sQ = dyn;              // [64][132]
    uint32_t* sK = dyn + 8448;       // [64][132]
    uint32_t* sV = dyn + 18432;      // [64][136]
    uint32_t* sP = dyn;              // 4 x [64][72] (alias Q+K+pad)
    uint32_t* sO = dyn;              // [64][132]   (alias P, after dead)

    int tid  = threadIdx.x;
    int lane = tid & 31, warp = tid >> 5;
    int g = lane >> 2, t = lane & 3;
    int widx = blockIdx.x;
    int bimg = widx >> 6, win = widx & 63;
    int ybase = (win >> 3) * 7, xbase = (win & 7) * 7;

    // ---- phase 1: load whole-window q/k/v (raw tf32 bits), rows >=49 zero ----
    {
        const uint4* qkv4 = (const uint4*)g_qkv;
        for (int idx = tid; idx < 2048; idx += 256) {
            int l = idx >> 5, c4 = (idx & 31) << 2;
            int h = c4 >> 5, d = c4 & 31;
            uint4 z = make_uint4(0u, 0u, 0u, 0u);
            uint4 q4 = z, k4 = z, v4 = z;
            if (l < 49) {
                size_t e = ((size_t)(widx * 4 + h) * 49 + l) * 32 + d;
                q4 = qkv4[e >> 2];
                k4 = qkv4[(e + 16384ull * 1568ull) >> 2];
                v4 = qkv4[(e + 2ull * 16384ull * 1568ull) >> 2];
            }
            *(uint4*)&sQ[l * 132 + c4] = q4;
            *(uint4*)&sK[l * 132 + c4] = k4;
            *(uint4*)&sV[l * 136 + c4] = v4;
        }
    }
    __syncthreads();

    int head = warp >> 1;
    int m0   = (warp & 1) * 32;
    const float* combp = g_comb + (size_t)(win * 4 + head) * 2401;

    // ---- phase 2: S = scale*QK^T + comb, register softmax (2 strips/warp) ----
    float acc[2][8][4] = {};
    float inv[2][2];
#pragma unroll
    for (int mt = 0; mt < 2; mt++) {
        int rb = m0 + mt * 16;
#pragma unroll
        for (int k0 = 0; k0 < 32; k0 += 8) {
            uint32_t a[4];
            int ab = (rb + g) * 132 + head * 32 + k0 + t;
            a[0] = sQ[ab];
            a[1] = sQ[ab + 8 * 132];
            a[2] = sQ[ab + 4];
            a[3] = sQ[ab + 8 * 132 + 4];
#pragma unroll
            for (int nt = 0; nt < 8; nt++) {
                uint32_t b[2];
                int bb = (nt * 8 + g) * 132 + head * 32 + k0 + t;
                b[0] = sK[bb];
                b[1] = sK[bb + 4];
                mma_tf32(acc[mt][nt], a, b);
            }
        }
        // comb for this strip (transient)
        float cmb[8][4];
#pragma unroll
        for (int h2 = 0; h2 < 2; h2++) {
            int i = rb + g + h2 * 8;
#pragma unroll
            for (int nt = 0; nt < 8; nt++)
#pragma unroll
                for (int e = 0; e < 2; e++) {
                    int j = nt * 8 + 2 * t + e;
                    cmb[nt][2 * h2 + e] = (i < 49 && j < 49)
                                        ? __ldg(combp + i * 49 + j) : -1e30f;
                }
        }
        const float scale = 0.17677669529663687f;
        float mx2[2] = {-1e30f, -1e30f};
#pragma unroll
        for (int nt = 0; nt < 8; nt++)
#pragma unroll
            for (int he = 0; he < 4; he++) {
                float v = acc[mt][nt][he] * scale + cmb[nt][he];
                acc[mt][nt][he] = v;
                mx2[he >> 1] = fmaxf(mx2[he >> 1], v);
            }
#pragma unroll
        for (int h2 = 0; h2 < 2; h2++) {
            mx2[h2] = fmaxf(mx2[h2], __shfl_xor_sync(0xffffffffu, mx2[h2], 1));
            mx2[h2] = fmaxf(mx2[h2], __shfl_xor_sync(0xffffffffu, mx2[h2], 2));
        }
        float sm2[2] = {0.f, 0.f};
#pragma unroll
        for (int nt = 0; nt < 8; nt++)
#pragma unroll
            for (int he = 0; he < 4; he++) {
                float p = __expf(acc[mt][nt][he] - mx2[he >> 1]);
                acc[mt][nt][he] = p;
                sm2[he >> 1] += p;
            }
#pragma unroll
        for (int h2 = 0; h2 < 2; h2++) {
            sm2[h2] += __shfl_xor_sync(0xffffffffu, sm2[h2], 1);
            sm2[h2] += __shfl_xor_sync(0xffffffffu, sm2[h2], 2);
        }
        inv[mt][0] = 1.f / sm2[0];
        inv[mt][1] = 1.f / sm2[1];
    }

    // all warps done reading sQ/sK -> P may overwrite them
    __syncthreads();

#pragma unroll
    for (int mt = 0; mt < 2; mt++)
#pragma unroll
        for (int h2 = 0; h2 < 2; h2++) {
            float iv = inv[mt][h2];
            int row = m0 + mt * 16 + g + h2 * 8;
#pragma unroll
            for (int nt = 0; nt < 8; nt++) {
                uint2 v = make_uint2(f2tf32(acc[mt][nt][2 * h2]     * iv),
                                     f2tf32(acc[mt][nt][2 * h2 + 1] * iv));
                *(uint2*)&sP[head * 4608 + row * 72 + nt * 8 + 2 * t] = v;
            }
        }
    __syncwarp();   // PV reads only this warp's own P rows

    // ---- phase 3: O = P @ V (per head, warp's 32 rows) ----
    float oac[2][4][4] = {};
#pragma unroll
    for (int mt = 0; mt < 2; mt++) {
        int rb = m0 + mt * 16;
#pragma unroll
        for (int k0 = 0; k0 < 64; k0 += 8) {
            uint32_t a[4];
            int ab = head * 4608 + (rb + g) * 72 + k0 + t;
            a[0] = sP[ab];
            a[1] = sP[ab + 8 * 72];
            a[2] = sP[ab + 4];
            a[3] = sP[ab + 8 * 72 + 4];
#pragma unroll
            for (int nt = 0; nt < 4; nt++) {
                uint32_t b[2];
                int bb = (k0 + t) * 136 + head * 32 + nt * 8 + g;
                b[0] = sV[bb];
                b[1] = sV[bb + 4 * 136];
                mma_tf32(oac[mt][nt], a, b);
            }
        }
    }

    // all warps done reading sP -> O may overwrite
    __syncthreads();
#pragma unroll
    for (int mt = 0; mt < 2; mt++)
#pragma unroll
        for (int h2 = 0; h2 < 2; h2++) {
            int row = m0 + mt * 16 + g + h2 * 8;
#pragma unroll
            for (int nt = 0; nt < 4; nt++) {
                uint2 v = make_uint2(f2tf32(oac[mt][nt][2 * h2]),
                                     f2tf32(oac[mt][nt][2 * h2 + 1]));
                *(uint2*)&sO[row * 132 + head * 32 + nt * 8 + 2 * t] = v;
            }
        }
    __syncthreads();

    // ---- phase 4: out = O @ proj_w + b (pipelined W, warps 2m x 4n) ----
    {
        int m0p = (warp >> 2) * 32, n0 = (warp & 3) * 32;
        const float* Wp = proj_w + n0 + g;
        float pacc[2][4][4] = {};
        uint32_t bv[8];
        {
            const float* w0 = Wp + (size_t)t * 128;
            const float* w1 = w0 + 4 * 128;
#pragma unroll
            for (int nt = 0; nt < 4; nt++) {
                bv[nt]     = f2tf32(__ldg(w0 + nt * 8));
                bv[4 + nt] = f2tf32(__ldg(w1 + nt * 8));
            }
        }
#pragma unroll
        for (int k0 = 0; k0 < 128; k0 += 8) {
            uint32_t bc[8];
#pragma unroll
            for (int j = 0; j < 8; j++) bc[j] = bv[j];
            if (k0 < 120) {
                const float* w0 = Wp + (size_t)(k0 + 8 + t) * 128;
                const float* w1 = w0 + 4 * 128;
#pragma unroll
                for (int nt = 0; nt < 4; nt++) {
                    bv[nt]     = f2tf32(__ldg(w0 + nt * 8));
                    bv[4 + nt] = f2tf32(__ldg(w1 + nt * 8));
                }
            }
            uint32_t a[2][4];
#pragma unroll
            for (int mt = 0; mt < 2; mt++) {
                int ab = (m0p + mt * 16 + g) * 132 + k0 + t;
                a[mt][0] = sO[ab];
                a[mt][1] = sO[ab + 8 * 132];
                a[mt][2] = sO[ab + 4];
                a[mt][3] = sO[ab + 8 * 132 + 4];
            }
#pragma unroll
            for (int mt = 0; mt < 2; mt++)
#pragma unroll
                for (int nt = 0; nt < 4; nt++) {
                    uint32_t bb2[2] = {bc[nt], bc[4 + nt]};
                    mma_tf32(pacc[mt][nt], a[mt], bb2);
                }
        }

        float bb[4][2];
#pragma unroll
        for (int nt = 0; nt < 4; nt++) {
            int d = n0 + nt * 8 + 2 * t;
            bb[nt][0] = __ldg(proj_b + d);
            bb[nt][1] = __ldg(proj_b + d + 1);
        }
#pragma unroll
        for (int mt = 0; mt < 2; mt++)
#pragma unroll
            for (int h2 = 0; h2 < 2; h2++) {
                int row = m0p + mt * 16 + g + h2 * 8;
                if (row < 49) {
                    int wy = row / 7, wx = row - wy * 7;
                    float* op = out + (((size_t)(bimg * 56 + ybase + wy)) * 56
                                       + xbase + wx) * 128;
#pragma unroll
                    for (int nt = 0; nt < 4; nt++) {
                        int d = n0 + nt * 8 + 2 * t;
                        *(float2*)&op[d] =
                            make_float2(pacc[mt][nt][2 * h2]     + bb[nt][0],
                                        pacc[mt][nt][2 * h2 + 1] + bb[nt][1]);
                    }
                }
            }
    }
}

// ---------------------------------------------------------------------------
extern "C" void kernel_launch(void* const* d_in, const int* in_sizes, int n_in,
                              void* d_out, int out_size)
{
    const float* x      = nullptr;
    const int*   relidx = nullptr;
    const float* mask   = nullptr;
    const float* qkv_w  = nullptr;
    const float* qkv_b  = nullptr;
    const float* relt   = nullptr;
    const float* proj_w = nullptr;
    const float* proj_b = nullptr;

    for (int i = 0; i < n_in; i++) {
        switch (in_sizes[i]) {
            case 25690112: x      = (const float*)d_in[i]; break;
            case 2401:     relidx = (const int*)  d_in[i]; break;
            case 153664:   mask   = (const float*)d_in[i]; break;
            case 49152:    qkv_w  = (const float*)d_in[i]; break;
            case 384:      qkv_b  = (const float*)d_in[i]; break;
            case 676:      relt   = (const float*)d_in[i]; break;
            case 16384:    proj_w = (const float*)d_in[i]; break;
            case 128:      proj_b = (const float*)d_in[i]; break;
            default: break;
        }
    }

    cudaFuncSetAttribute(qkv_gemm_mma, cudaFuncAttributeMaxDynamicSharedMemorySize, SM_A_BYTES);
    cudaFuncSetAttribute(attnproj_mma, cudaFuncAttributeMaxDynamicSharedMemorySize, FA_BYTES);

    combine_bias<<<(COMB_ELEMS + 255) / 256, 256>>>(relidx, mask, relt);

    qkv_gemm_mma<<<TOKENS / 128, 256, SM_A_BYTES>>>(x, qkv_w, qkv_b);

    attnproj_mma<<<NWIN, 256, FA_BYTES>>>(proj_w, proj_b, (float*)d_out);
}